// round 16
// baseline (speedup 1.0000x reference)
#include <cuda_runtime.h>
#include <cuda_bf16.h>
#include <cstdint>

// ============================================================
// TernaryLinear on GB300 — sm_103 base-target (no tcgen05).
// v3: int8 IMMA path.
//   x -> fixed point x_int = round(x*1024) = 64*h + l  (h,l int8)
//   weights -> t1 = tern(w) in {-1,0,1},  t64 = 64*t in {-64,0,64}
//   acc(int32) = h @ t64 + l @ t1  ==  x_int @ t   (exact)
//   y = acc * (scale_row / 1024) + bias
//   GEMM: 128x128 CTA, 4 warps (2Mx2N), warp tile 64x64, BK=64 int8,
//   4-stage cp.async, ldmatrix + mma.m16n8k32.s8, int32 accum.
// Measured: v1 242.4us, v2 234.1us (rel_err 8.9e-6).
// ============================================================

#define B_DIM 4096
#define I_DIM 4096
#define O_DIM 1024

__device__ __align__(128) int8_t g_t1[(size_t)O_DIM * I_DIM];    // 4MB
__device__ __align__(128) int8_t g_t64[(size_t)O_DIM * I_DIM];   // 4MB
__device__ float g_scale[O_DIM];
__device__ __align__(128) int8_t g_xh[(size_t)B_DIM * I_DIM];    // 16MB
__device__ __align__(128) int8_t g_xl[(size_t)B_DIM * I_DIM];    // 16MB

__device__ __forceinline__ uint32_t smem_to_u32(const void* p) {
    uint32_t a;
    asm("{ .reg .u64 t; cvta.to.shared.u64 t, %1; cvt.u32.u64 %0, t; }" : "=r"(a) : "l"(p));
    return a;
}
__device__ __forceinline__ void cp16(uint32_t dst, const void* src) {
    asm volatile("cp.async.cg.shared.global [%0], [%1], 16;" :: "r"(dst), "l"(src) : "memory");
}
__device__ __forceinline__ void cp_commit() {
    asm volatile("cp.async.commit_group;" ::: "memory");
}
__device__ __forceinline__ void ldsm4(uint32_t* r, uint32_t addr) {
    asm volatile("ldmatrix.sync.aligned.m8n8.x4.shared.b16 {%0,%1,%2,%3}, [%4];"
                 : "=r"(r[0]), "=r"(r[1]), "=r"(r[2]), "=r"(r[3]) : "r"(addr));
}
// int8 IMMA: D(s32) = A(s8,16x32) * B(s8,32x8) + C
__device__ __forceinline__ void mma16832(int* c, const uint32_t* a, uint32_t b0, uint32_t b1) {
    asm volatile(
        "mma.sync.aligned.m16n8k32.row.col.s32.s8.s8.s32 "
        "{%0,%1,%2,%3}, {%4,%5,%6,%7}, {%8,%9}, {%0,%1,%2,%3};"
        : "+r"(c[0]), "+r"(c[1]), "+r"(c[2]), "+r"(c[3])
        : "r"(a[0]), "r"(a[1]), "r"(a[2]), "r"(a[3]), "r"(b0), "r"(b1));
}

// ============================================================
// Kernel 1: ternary quantization -> t1 and t64 int8 planes
// ============================================================
__global__ void quant_kernel(const float* __restrict__ w) {
    __shared__ float redf[256];
    __shared__ int   redi[256];
    const int o = blockIdx.x;
    const int tid = threadIdx.x;
    const float4* wr = reinterpret_cast<const float4*>(w + (size_t)o * I_DIM);

    float4 v[4];
    float s = 0.f;
#pragma unroll
    for (int q = 0; q < 4; q++) {
        v[q] = wr[tid + 256 * q];
        s += fabsf(v[q].x) + fabsf(v[q].y) + fabsf(v[q].z) + fabsf(v[q].w);
    }
    redf[tid] = s;
    __syncthreads();
    for (int off = 128; off; off >>= 1) {
        if (tid < off) redf[tid] += redf[tid + off];
        __syncthreads();
    }
    const float delta = 0.05f * redf[0] * (1.0f / (float)I_DIM);
    __syncthreads();

    float sk = 0.f;
    int cnt = 0;
    uint32_t* t1w  = reinterpret_cast<uint32_t*>(g_t1  + (size_t)o * I_DIM);
    uint32_t* t64w = reinterpret_cast<uint32_t*>(g_t64 + (size_t)o * I_DIM);
#pragma unroll
    for (int q = 0; q < 4; q++) {
        float e[4] = {v[q].x, v[q].y, v[q].z, v[q].w};
        uint32_t p1 = 0, p64 = 0;
#pragma unroll
        for (int j = 0; j < 4; j++) {
            float a = fabsf(e[j]);
            int sgn = 0;
            if (a > delta) {
                sk += a;
                cnt++;
                sgn = (e[j] > 0.f) ? 1 : -1;
            }
            p1  |= ((uint32_t)(uint8_t)(int8_t)sgn) << (8 * j);
            p64 |= ((uint32_t)(uint8_t)(int8_t)(sgn << 6)) << (8 * j);
        }
        t1w[tid + 256 * q]  = p1;
        t64w[tid + 256 * q] = p64;
    }
    redf[tid] = sk;
    redi[tid] = cnt;
    __syncthreads();
    for (int off = 128; off; off >>= 1) {
        if (tid < off) { redf[tid] += redf[tid + off]; redi[tid] += redi[tid + off]; }
        __syncthreads();
    }
    if (tid == 0) {
        int n = redi[0] > 1 ? redi[0] : 1;
        g_scale[o] = redf[0] / (float)n;
    }
}

// ============================================================
// Kernel 2: split x into base-64 int8 digits (s = 2^-10)
//   x_int = clamp(round(x*1024), -8160, 8159) = 64*h + l
// ============================================================
__global__ void split_kernel(const float4* __restrict__ x) {
    const unsigned i = blockIdx.x * blockDim.x + threadIdx.x;
    float4 v = x[i];
    float e[4] = {v.x, v.y, v.z, v.w};
    uint32_t ph = 0, pl = 0;
#pragma unroll
    for (int j = 0; j < 4; j++) {
        int xi = (int)rintf(e[j] * 1024.f);
        xi = min(max(xi, -8160), 8159);
        int h = (xi + 32) >> 6;          // floor((xi+32)/64) in [-127,127]
        int lo = xi - (h << 6);          // in [-32,31]
        ph |= ((uint32_t)(uint8_t)(int8_t)h)  << (8 * j);
        pl |= ((uint32_t)(uint8_t)(int8_t)lo) << (8 * j);
    }
    reinterpret_cast<uint32_t*>(g_xh)[i] = ph;
    reinterpret_cast<uint32_t*>(g_xl)[i] = pl;
}

// ============================================================
// Kernel 3: int8 mma GEMM
//   CTA 128x128, 4 warps (2Mx2N), warp tile 64x64, BK=64 int8
//   virtual K = 8192: iters 0..63 (h @ t64), 64..127 (l @ t1)
//   SMEM rows: 64 int8 (64B) + 16B pad = 80B (conflict-free)
// ============================================================
#define GK_ITERS    128
#define GK_ROWB     80u
#define GK_AT       (128u * GK_ROWB)           // 10240 per operand tile
#define GK_STAGE    (2u * GK_AT)               // 20480 per stage
#define GK_STAGES   4
#define GK_SCALE    (GK_STAGES * GK_STAGE)     // 81920
#define GK_BIAS     (GK_SCALE + 512)
#define GK_SMEM     (GK_BIAS + 512)            // 82944

struct GLoad {
    const int8_t* ah;
    const int8_t* al;
    const int8_t* b64;
    const int8_t* b1;
    uint32_t dstA, dstB;
};

// 128 threads: thread t -> rows r0, r0+32, r0+64, r0+96 (A and B), 16B chunk kc
__device__ __forceinline__ void gk_load_stage(const GLoad& g, int i) {
    const uint32_t st = (uint32_t)(i & 3) * GK_STAGE;
    const int8_t* a = ((i < 64) ? g.ah : g.al) + (size_t)(i & 63) * 64;
    const int8_t* b = ((i < 64) ? g.b64 : g.b1) + (size_t)(i & 63) * 64;
#pragma unroll
    for (int q = 0; q < 4; q++) {
        cp16(g.dstA + st + (uint32_t)q * 32u * GK_ROWB, a + (size_t)q * 32 * I_DIM);
        cp16(g.dstB + st + (uint32_t)q * 32u * GK_ROWB, b + (size_t)q * 32 * I_DIM);
    }
    cp_commit();
}

__global__ __launch_bounds__(128, 2)
void gemm_kernel(const float* __restrict__ bias, float* __restrict__ out) {
    extern __shared__ char smem[];
    const uint32_t sb = smem_to_u32(smem);
    const int tid = threadIdx.x;
    const int wid = tid >> 5;
    const int l   = tid & 31;
    const int wm  = wid >> 1;   // 0..1 -> M halves of 64
    const int wn  = wid & 1;    // 0..1 -> N halves of 64

    // fused scale (g_scale * 2^-10) and bias into SMEM
    reinterpret_cast<float*>(smem + GK_SCALE)[tid] =
        g_scale[blockIdx.y * 128 + tid] * (1.0f / 1024.0f);
    reinterpret_cast<float*>(smem + GK_BIAS)[tid] = bias[blockIdx.y * 128 + tid];

    // ---- loader geometry (row = 64B data = 4 x 16B chunks)
    const int r0 = tid >> 2;        // 0..31
    const int kc = tid & 3;
    GLoad g;
    g.ah  = g_xh  + ((size_t)(blockIdx.x * 128 + r0)) * I_DIM + kc * 16;
    g.al  = g_xl  + ((size_t)(blockIdx.x * 128 + r0)) * I_DIM + kc * 16;
    g.b64 = g_t64 + ((size_t)(blockIdx.y * 128 + r0)) * I_DIM + kc * 16;
    g.b1  = g_t1  + ((size_t)(blockIdx.y * 128 + r0)) * I_DIM + kc * 16;
    g.dstA = sb + (uint32_t)r0 * GK_ROWB + (uint32_t)kc * 16;
    g.dstB = g.dstA + GK_AT;

    // ---- ldmatrix byte offsets (within a stage); ks adds +32B (k32 step)
    // A: lane l -> row (l&15), k-half (l>>4)*16B; matrices = a0..a3 of s8 frag
    uint32_t aoff[4];
#pragma unroll
    for (int mt = 0; mt < 4; mt++)
        aoff[mt] = (uint32_t)(wm * 64 + mt * 16 + (l & 15)) * GK_ROWB + (uint32_t)((l >> 4) * 16);
    // B: j=l>>3: n-row = p*16 + (j>>1)*8 + (l&7), k-half (j&1)*16B
    uint32_t boff[4];
#pragma unroll
    for (int p = 0; p < 4; p++) {
        const int j = l >> 3;
        boff[p] = GK_AT +
                  (uint32_t)(wn * 64 + p * 16 + ((j >> 1) * 8) + (l & 7)) * GK_ROWB +
                  (uint32_t)((j & 1) * 16);
    }

    int c[4][8][4] = {};

    gk_load_stage(g, 0);
    gk_load_stage(g, 1);
    gk_load_stage(g, 2);

    for (int i = 0; i < GK_ITERS; i++) {
        if (i <= GK_ITERS - 3)      asm volatile("cp.async.wait_group 2;" ::: "memory");
        else if (i == GK_ITERS - 2) asm volatile("cp.async.wait_group 1;" ::: "memory");
        else                        asm volatile("cp.async.wait_group 0;" ::: "memory");
        __syncthreads();

        // prefetch first: overlap DMA with the MMA block
        if (i + 3 < GK_ITERS) gk_load_stage(g, i + 3);

        const uint32_t st = sb + (uint32_t)(i & 3) * GK_STAGE;
#pragma unroll
        for (int ks = 0; ks < 2; ks++) {   // two k32 steps per 64B row
            uint32_t a[4][4], b[4][4];
#pragma unroll
            for (int mt = 0; mt < 4; mt++) ldsm4(a[mt], st + aoff[mt] + ks * 32);
#pragma unroll
            for (int p = 0; p < 4; p++)    ldsm4(b[p], st + boff[p] + ks * 32);
#pragma unroll
            for (int mt = 0; mt < 4; mt++)
#pragma unroll
                for (int nt = 0; nt < 8; nt++)
                    mma16832(c[mt][nt], a[mt], b[nt >> 1][(nt & 1) * 2], b[nt >> 1][(nt & 1) * 2 + 1]);
        }
    }

    // ---- epilogue: y = float(acc) * (scale/1024) + bias
    const float* ss = reinterpret_cast<const float*>(smem + GK_SCALE);
    const float* bb = reinterpret_cast<const float*>(smem + GK_BIAS);
#pragma unroll
    for (int mt = 0; mt < 4; mt++) {
        const int mrow = blockIdx.x * 128 + wm * 64 + mt * 16 + (l >> 2);
#pragma unroll
        for (int nt = 0; nt < 8; nt++) {
            const int cn = wn * 64 + nt * 8 + 2 * (l & 3);
            const float s0 = ss[cn], s1 = ss[cn + 1];
            const float b0 = bb[cn], b1 = bb[cn + 1];
            float* p0 = out + (size_t)mrow * O_DIM + blockIdx.y * 128 + cn;
            float2 v0, v1;
            v0.x = fmaf(__int2float_rn(c[mt][nt][0]), s0, b0);
            v0.y = fmaf(__int2float_rn(c[mt][nt][1]), s1, b1);
            v1.x = fmaf(__int2float_rn(c[mt][nt][2]), s0, b0);
            v1.y = fmaf(__int2float_rn(c[mt][nt][3]), s1, b1);
            *reinterpret_cast<float2*>(p0) = v0;
            *reinterpret_cast<float2*>(p0 + (size_t)8 * O_DIM) = v1;
        }
    }
}

// ============================================================
// launch
// ============================================================
extern "C" void kernel_launch(void* const* d_in, const int* in_sizes, int n_in,
                              void* d_out, int out_size) {
    const float* x    = (const float*)d_in[0];  // [4096, 4096]
    const float* w    = (const float*)d_in[1];  // [1024, 4096]
    const float* bias = (const float*)d_in[2];  // [1024]
    float* out        = (float*)d_out;          // [4096, 1024]

    (void)in_sizes; (void)n_in; (void)out_size;

    quant_kernel<<<O_DIM, 256>>>(w);
    split_kernel<<<(B_DIM * I_DIM / 4) / 512, 512>>>((const float4*)x);

    cudaFuncSetAttribute(gemm_kernel, cudaFuncAttributeMaxDynamicSharedMemorySize, GK_SMEM);
    gemm_kernel<<<dim3(32, 8), 128, GK_SMEM>>>(bias, out);
}